// round 13
// baseline (speedup 1.0000x reference)
#include <cuda_runtime.h>
#include <cuda_bf16.h>
#include <math.h>
#include <stdint.h>

// ---------------- problem constants ----------------
#define B_ROWS 16384
#define DIM    768
#define NP     8192
#define NCAND  8            // candidates per row handed to rescore
#define SCOFF  3.0f

// ---------------- GEMM tiling ----------------
#define BM 128
#define BN 256
#define BK 64               // bf16 elems per chunk row (= 128 bytes)
#define NSTAGE 3
#define NTHREADS 1024
#define NT_TILES (NP / BN)        // 32
#define KCH      (DIM / BK)       // 12
#define NCHUNK   (NT_TILES * KCH) // 384
#define APITCH_B 128              // bytes per smem row (swizzled, no pad)
#define A_STAGE_B (BM * APITCH_B)            // 16384
#define B_STAGE_B (BN * APITCH_B)            // 32768
#define STAGE_BYTES (A_STAGE_B + B_STAGE_B)  // 49152
#define SC_STRIDE 264             // bf16 elems per sc row

// smem layout (bytes)
#define SM_SC    (NSTAGE * STAGE_BYTES)              // 147456
#define SM_BIAS  (SM_SC + BM * SC_STRIDE * 2)        // 215040
#define SM_LV    (SM_BIAS + BN * 4)                  // 216064
#define SM_LI    (SM_LV + BM * NCAND * 4)            // 220160
#define SM_TOTAL (SM_LI + BM * NCAND * 4)            // 224256

// ---------------- device scratch ----------------
__device__ __nv_bfloat16 g_V16[(size_t)B_ROWS * DIM];
__device__ __nv_bfloat16 g_W16[(size_t)NP * DIM];
__device__ int           g_cand[(size_t)B_ROWS * NCAND];

// ---------------- helpers ----------------
static __device__ __forceinline__ uint32_t s2u(const void* p){
    uint32_t a;
    asm("{ .reg .u64 t; cvta.to.shared.u64 t, %1; cvt.u32.u64 %0, t; }"
        : "=r"(a) : "l"(p));
    return a;
}
static __device__ __forceinline__ void cpa16(uint32_t dst, const void* src){
    asm volatile("cp.async.cg.shared.global [%0], [%1], 16;"
        :: "r"(dst), "l"(src) : "memory");
}
#define CPA_COMMIT() asm volatile("cp.async.commit_group;" ::: "memory")
#define CPA_WAIT1()  asm volatile("cp.async.wait_group 1;" ::: "memory")

static __device__ __forceinline__ void ldsm4(uint32_t* r, uint32_t addr){
    asm volatile("ldmatrix.sync.aligned.m8n8.x4.shared.b16 {%0,%1,%2,%3}, [%4];"
        : "=r"(r[0]), "=r"(r[1]), "=r"(r[2]), "=r"(r[3]) : "r"(addr));
}
static __device__ __forceinline__ void mma16816(float* d, const uint32_t* a,
                                                uint32_t b0, uint32_t b1){
    asm volatile(
        "mma.sync.aligned.m16n8k16.row.col.f32.bf16.bf16.f32 "
        "{%0,%1,%2,%3}, {%4,%5,%6,%7}, {%8,%9}, {%0,%1,%2,%3};"
        : "+f"(d[0]), "+f"(d[1]), "+f"(d[2]), "+f"(d[3])
        : "r"(a[0]), "r"(a[1]), "r"(a[2]), "r"(a[3]), "r"(b0), "r"(b1));
}

// ---------------- kernel 0: dummy (ncu launch alignment) ----------------
__global__ void dummy_kernel() {}

// ---------------- kernel 1: fp32 -> bf16 convert ----------------
__global__ void convert_kernel(const float* __restrict__ V,
                               const float* __restrict__ W)
{
    const size_t NV4 = (size_t)B_ROWS * DIM / 4;
    const size_t NW4 = (size_t)NP * DIM / 4;
    const size_t stride = (size_t)gridDim.x * blockDim.x;
    for (size_t i = blockIdx.x * (size_t)blockDim.x + threadIdx.x;
         i < NV4 + NW4; i += stride){
        if (i < NV4){
            float4 f = ((const float4*)V)[i];
            __nv_bfloat162* d = (__nv_bfloat162*)g_V16 + i*2;
            d[0] = __float22bfloat162_rn(make_float2(f.x, f.y));
            d[1] = __float22bfloat162_rn(make_float2(f.z, f.w));
        } else {
            size_t j = i - NV4;
            float4 f = ((const float4*)W)[j];
            __nv_bfloat162* d = (__nv_bfloat162*)g_W16 + j*2;
            d[0] = __float22bfloat162_rn(make_float2(f.x, f.y));
            d[1] = __float22bfloat162_rn(make_float2(f.z, f.w));
        }
    }
}

// ---------------- kernel 2: bf16 mma.sync GEMM (32 warps, warp tile 32x32) ----------------
__global__ __launch_bounds__(NTHREADS, 1)
void gemm_topk_kernel(const float* __restrict__ bias)
{
    extern __shared__ char smem[];
    const uint32_t sbase = s2u(smem);
    const int tid  = threadIdx.x;
    const int lane = tid & 31;
    const int wid  = tid >> 5;
    const int g    = lane >> 2;
    const int tq   = lane & 3;
    const int wm   = wid & 3;        // M block (32 rows)
    const int wn   = wid >> 2;       // N block (32 cols)
    const int row0 = blockIdx.x * BM;

    float* bias_s = (float*)(smem + SM_BIAS);
    float* lv_s   = (float*)(smem + SM_LV);
    int*   li_s   = (int*)(smem + SM_LI);

    if (tid < BM){
        #pragma unroll
        for (int k = 0; k < NCAND; ++k){
            lv_s[tid*NCAND + k] = -INFINITY;
            li_s[tid*NCAND + k] = 0;
        }
    }
    float thr = -INFINITY;

    // ldmatrix lane->row/k decomposition (swizzled 128B rows)
    const uint32_t aRow  = (uint32_t)(wm*32 + (lane & 15));        // + mi*16
    const uint32_t aKb   = (uint32_t)(lane >> 4);                  // k 16B-unit low bit
    const uint32_t aSw   = aRow & 7;                               // invariant under +16
    const uint32_t bRow  = (uint32_t)(wn*32 + (lane & 7) + ((lane & 16) >> 1)); // + nip*16
    const uint32_t bKb   = (uint32_t)((lane >> 3) & 1);
    const uint32_t bSw   = bRow & 7;

    // one chunk: A 128x128B + B 256x128B  (3072 x 16B cp.async, 3/thread)
    auto issue_chunk = [&](int c){
        const int nt = c / KCH;
        const int kt = c - nt * KCH;
        const uint32_t stg = sbase + (uint32_t)(c % NSTAGE) * STAGE_BYTES;
        {   // A: ops 0..1023
            const int r = tid >> 3, kc = tid & 7;
            cpa16(stg + (uint32_t)r*128u + (uint32_t)((kc ^ (r & 7)) << 4),
                  g_V16 + (size_t)(row0 + r)*DIM + kt*BK + kc*8);
        }
        #pragma unroll
        for (int i = 0; i < 2; ++i){     // B: ops 0..2047
            const int o = tid + i*1024;
            const int r = o >> 3, kc = o & 7;
            cpa16(stg + A_STAGE_B + (uint32_t)r*128u + (uint32_t)((kc ^ (r & 7)) << 4),
                  g_W16 + (size_t)(nt*BN + r)*DIM + kt*BK + kc*8);
        }
        CPA_COMMIT();
    };

    issue_chunk(0); issue_chunk(1);    // prologue: 2 chunks in flight

    for (int nt = 0; nt < NT_TILES; ++nt){
        float acc[2][4][4];
        #pragma unroll
        for (int mi = 0; mi < 2; ++mi)
            #pragma unroll
            for (int ni = 0; ni < 4; ++ni)
                #pragma unroll
                for (int q = 0; q < 4; ++q) acc[mi][ni][q] = 0.0f;

        #pragma unroll 1
        for (int kt = 0; kt < KCH; ++kt){
            const int c = nt * KCH + kt;
            CPA_WAIT1();                 // chunk c resident (c+1 may be in flight)
            __syncthreads();
            if (kt == 0 && tid < 256) bias_s[tid] = bias[nt*BN + tid];

            if (c + 2 < NCHUNK) issue_chunk(c + 2);   // 2-ahead into stage (c+2)%3

            const uint32_t stg  = sbase + (uint32_t)(c % NSTAGE) * STAGE_BYTES;
            const uint32_t stgB = stg + A_STAGE_B;

            #pragma unroll
            for (int ks = 0; ks < 4; ++ks){   // four k16 steps per 128B row
                const uint32_t akx = ((uint32_t)(ks*2) + aKb) ^ aSw;
                const uint32_t bkx = ((uint32_t)(ks*2) + bKb) ^ bSw;
                uint32_t a[2][4], b[4][2];
                #pragma unroll
                for (int mi = 0; mi < 2; ++mi)
                    ldsm4(a[mi], stg + (aRow + mi*16)*128u + (akx << 4));
                #pragma unroll
                for (int nip = 0; nip < 2; ++nip){
                    uint32_t r4[4];
                    ldsm4(r4, stgB + (bRow + nip*16)*128u + (bkx << 4));
                    b[nip*2  ][0] = r4[0]; b[nip*2  ][1] = r4[1];
                    b[nip*2+1][0] = r4[2]; b[nip*2+1][1] = r4[3];
                }
                #pragma unroll
                for (int ni = 0; ni < 4; ++ni)
                    #pragma unroll
                    for (int mi = 0; mi < 2; ++mi)
                        mma16816(acc[mi][ni], a[mi], b[ni][0], b[ni][1]);
            }
        }

        // ---- stage scores (offset bf16, bias folded) ----
        #pragma unroll
        for (int mi = 0; mi < 2; ++mi){
            const int row = wm*32 + mi*16 + g;
            #pragma unroll
            for (int ni = 0; ni < 4; ++ni){
                const int col = wn*32 + ni*8 + 2*tq;
                const float b0 = bias_s[col]     - SCOFF;
                const float b1 = bias_s[col + 1] - SCOFF;
                __nv_bfloat162* p0 =
                    (__nv_bfloat162*)(smem + SM_SC + ((size_t)row*SC_STRIDE + col)*2);
                __nv_bfloat162* p1 =
                    (__nv_bfloat162*)(smem + SM_SC + ((size_t)(row+8)*SC_STRIDE + col)*2);
                *p0 = __float22bfloat162_rn(
                        make_float2(acc[mi][ni][0] + b0, acc[mi][ni][1] + b1));
                *p1 = __float22bfloat162_rn(
                        make_float2(acc[mi][ni][2] + b0, acc[mi][ni][3] + b1));
            }
        }
        __syncthreads();

        // ---- per-row top-8 scan (threads 0..127) ----
        if (tid < BM){
            const __nv_bfloat162* srow =
                (const __nv_bfloat162*)(smem + SM_SC + (size_t)tid*SC_STRIDE*2);
            const int base = tid * NCAND;
            const int n0   = nt * BN;
            #pragma unroll 4
            for (int j = 0; j < BN/2; ++j){
                const float2 f = __bfloat1622float2(srow[j]);
                if (f.x > thr){
                    int k = NCAND-1;
                    while (k > 0 && lv_s[base+k-1] < f.x){
                        lv_s[base+k] = lv_s[base+k-1];
                        li_s[base+k] = li_s[base+k-1];
                        --k;
                    }
                    lv_s[base+k] = f.x; li_s[base+k] = n0 + 2*j;
                    thr = lv_s[base+NCAND-1];
                }
                if (f.y > thr){
                    int k = NCAND-1;
                    while (k > 0 && lv_s[base+k-1] < f.y){
                        lv_s[base+k] = lv_s[base+k-1];
                        li_s[base+k] = li_s[base+k-1];
                        --k;
                    }
                    lv_s[base+k] = f.y; li_s[base+k] = n0 + 2*j + 1;
                    thr = lv_s[base+NCAND-1];
                }
            }
        }
        __syncthreads();
    }

    if (tid < BM){
        #pragma unroll
        for (int k = 0; k < NCAND; ++k)
            g_cand[(size_t)(row0 + tid)*NCAND + k] = li_s[tid*NCAND + k];
    }
}

// ---------------- kernel 3: exact rescore + softmax + combine (float4) ----------------
__global__ __launch_bounds__(256)
void rescore_kernel(const float* __restrict__ V,
                    const float* __restrict__ W,
                    const float* __restrict__ bias,
                    const float* __restrict__ pool,
                    float* __restrict__ out)
{
    const int lane = threadIdx.x & 31;
    const int wid  = threadIdx.x >> 5;
    const int row  = blockIdx.x * 8 + wid;

    int ids[NCAND];
    #pragma unroll
    for (int k = 0; k < NCAND; ++k)
        ids[k] = g_cand[(size_t)row*NCAND + k];

    float4 a4[NCAND];
    #pragma unroll
    for (int k = 0; k < NCAND; ++k) a4[k] = make_float4(0.f, 0.f, 0.f, 0.f);
    const float4* vrow = (const float4*)(V + (size_t)row * DIM);
    #pragma unroll
    for (int i = 0; i < DIM/128; ++i){
        const int d4 = i*32 + lane;
        const float4 v = vrow[d4];
        #pragma unroll
        for (int k = 0; k < NCAND; ++k){
            const float4 w = __ldg((const float4*)(W + (size_t)ids[k]*DIM) + d4);
            a4[k].x = fmaf(v.x, w.x, a4[k].x);
            a4[k].y = fmaf(v.y, w.y, a4[k].y);
            a4[k].z = fmaf(v.z, w.z, a4[k].z);
            a4[k].w = fmaf(v.w, w.w, a4[k].w);
        }
    }
    float acc[NCAND];
    #pragma unroll
    for (int k = 0; k < NCAND; ++k){
        float s = (a4[k].x + a4[k].y) + (a4[k].z + a4[k].w);
        #pragma unroll
        for (int off = 16; off; off >>= 1)
            s += __shfl_xor_sync(0xffffffffu, s, off);
        acc[k] = s + bias[ids[k]];
    }
    #pragma unroll
    for (int a = 0; a < NCAND; ++a)
        #pragma unroll
        for (int j = 0; j < NCAND-1; ++j)
            if (acc[j] < acc[j+1]){
                float tv = acc[j]; acc[j] = acc[j+1]; acc[j+1] = tv;
                int   tx = ids[j]; ids[j] = ids[j+1]; ids[j+1] = tx;
            }
    const float m = acc[0];
    float e0 = expf(acc[0]-m), e1 = expf(acc[1]-m), e2 = expf(acc[2]-m),
          e3 = expf(acc[3]-m), e4 = expf(acc[4]-m);
    const float inv = 1.0f / (e0+e1+e2+e3+e4);
    e0 *= inv; e1 *= inv; e2 *= inv; e3 *= inv; e4 *= inv;
    const float4* p0 = (const float4*)(pool + (size_t)ids[0]*DIM);
    const float4* p1 = (const float4*)(pool + (size_t)ids[1]*DIM);
    const float4* p2 = (const float4*)(pool + (size_t)ids[2]*DIM);
    const float4* p3 = (const float4*)(pool + (size_t)ids[3]*DIM);
    const float4* p4 = (const float4*)(pool + (size_t)ids[4]*DIM);
    float4* orow = (float4*)(out + (size_t)row * DIM);
    #pragma unroll
    for (int i = 0; i < DIM/128; ++i){
        const int d4 = i*32 + lane;
        const float4 q0 = p0[d4], q1 = p1[d4], q2 = p2[d4], q3 = p3[d4], q4 = p4[d4];
        float4 o;
        o.x = e0*q0.x; o.y = e0*q0.y; o.z = e0*q0.z; o.w = e0*q0.w;
        o.x = fmaf(e1,q1.x,o.x); o.y = fmaf(e1,q1.y,o.y); o.z = fmaf(e1,q1.z,o.z); o.w = fmaf(e1,q1.w,o.w);
        o.x = fmaf(e2,q2.x,o.x); o.y = fmaf(e2,q2.y,o.y); o.z = fmaf(e2,q2.z,o.z); o.w = fmaf(e2,q2.w,o.w);
        o.x = fmaf(e3,q3.x,o.x); o.y = fmaf(e3,q3.y,o.y); o.z = fmaf(e3,q3.z,o.z); o.w = fmaf(e3,q3.w,o.w);
        o.x = fmaf(e4,q4.x,o.x); o.y = fmaf(e4,q4.y,o.y); o.z = fmaf(e4,q4.z,o.z); o.w = fmaf(e4,q4.w,o.w);
        orow[d4] = o;
    }
}

// ---------------- launch ----------------
extern "C" void kernel_launch(void* const* d_in, const int* in_sizes, int n_in,
                              void* d_out, int out_size)
{
    const float* V    = (const float*)d_in[0];
    const float* W    = (const float*)d_in[1];
    const float* bias = (const float*)d_in[2];
    const float* pool = (const float*)d_in[3];
    float* out = (float*)d_out;

    cudaFuncSetAttribute(gemm_topk_kernel,
                         cudaFuncAttributeMaxDynamicSharedMemorySize, SM_TOTAL);

    dummy_kernel<<<1, 32>>>();
    dummy_kernel<<<1, 32>>>();
    convert_kernel<<<1184, 256>>>(V, W);
    gemm_topk_kernel<<<B_ROWS / BM, NTHREADS, SM_TOTAL>>>(bias);   // launch #4 -> ncu
    rescore_kernel<<<B_ROWS / 8, 256>>>(V, W, bias, pool, out);
}

// round 14
// speedup vs baseline: 1.0516x; 1.0516x over previous
#include <cuda_runtime.h>
#include <cuda_bf16.h>
#include <math.h>
#include <stdint.h>

// ---------------- problem constants ----------------
#define B_ROWS 16384
#define DIM    768
#define NP     8192
#define NCAND  8            // candidates per row handed to rescore
#define SCOFF  3.0f

// ---------------- GEMM tiling ----------------
#define BM 128
#define BN 256
#define BK 64               // bf16 elems per chunk row (= 128 bytes)
#define NSTAGE 3
#define NTHREADS 512
#define NT_TILES (NP / BN)        // 32
#define KCH      (DIM / BK)       // 12
#define NCHUNK   (NT_TILES * KCH) // 384
#define APITCH_B 128              // bytes per smem row (swizzled, no pad)
#define A_STAGE_B (BM * APITCH_B)            // 16384
#define B_STAGE_B (BN * APITCH_B)            // 32768
#define STAGE_BYTES (A_STAGE_B + B_STAGE_B)  // 49152
#define SC_STRIDE 264             // bf16 elems per sc row

// smem layout (bytes)
#define SM_SC    (NSTAGE * STAGE_BYTES)              // 147456
#define SM_BIAS  (SM_SC + BM * SC_STRIDE * 2)        // 215040
#define SM_LV    (SM_BIAS + BN * 4)                  // 216064
#define SM_LI    (SM_LV + BM * NCAND * 4)            // 220160
#define SM_TOTAL (SM_LI + BM * NCAND * 4)            // 224256

// ---------------- device scratch ----------------
__device__ __nv_bfloat16 g_V16[(size_t)B_ROWS * DIM];
__device__ __nv_bfloat16 g_W16[(size_t)NP * DIM];

// ---------------- helpers ----------------
static __device__ __forceinline__ uint32_t s2u(const void* p){
    uint32_t a;
    asm("{ .reg .u64 t; cvta.to.shared.u64 t, %1; cvt.u32.u64 %0, t; }"
        : "=r"(a) : "l"(p));
    return a;
}
static __device__ __forceinline__ void cpa16(uint32_t dst, const void* src){
    asm volatile("cp.async.cg.shared.global [%0], [%1], 16;"
        :: "r"(dst), "l"(src) : "memory");
}
#define CPA_COMMIT() asm volatile("cp.async.commit_group;" ::: "memory")
#define CPA_WAIT1()  asm volatile("cp.async.wait_group 1;" ::: "memory")

static __device__ __forceinline__ void ldsm4(uint32_t* r, uint32_t addr){
    asm volatile("ldmatrix.sync.aligned.m8n8.x4.shared.b16 {%0,%1,%2,%3}, [%4];"
        : "=r"(r[0]), "=r"(r[1]), "=r"(r[2]), "=r"(r[3]) : "r"(addr));
}
static __device__ __forceinline__ void mma16816(float* d, const uint32_t* a,
                                                uint32_t b0, uint32_t b1){
    asm volatile(
        "mma.sync.aligned.m16n8k16.row.col.f32.bf16.bf16.f32 "
        "{%0,%1,%2,%3}, {%4,%5,%6,%7}, {%8,%9}, {%0,%1,%2,%3};"
        : "+f"(d[0]), "+f"(d[1]), "+f"(d[2]), "+f"(d[3])
        : "r"(a[0]), "r"(a[1]), "r"(a[2]), "r"(a[3]), "r"(b0), "r"(b1));
}

// ---------------- kernel 0: dummy (ncu launch alignment) ----------------
__global__ void dummy_kernel() {}

// ---------------- kernel 1: fp32 -> bf16 convert ----------------
__global__ void convert_kernel(const float* __restrict__ V,
                               const float* __restrict__ W)
{
    const size_t NV4 = (size_t)B_ROWS * DIM / 4;
    const size_t NW4 = (size_t)NP * DIM / 4;
    const size_t stride = (size_t)gridDim.x * blockDim.x;
    for (size_t i = blockIdx.x * (size_t)blockDim.x + threadIdx.x;
         i < NV4 + NW4; i += stride){
        if (i < NV4){
            float4 f = ((const float4*)V)[i];
            __nv_bfloat162* d = (__nv_bfloat162*)g_V16 + i*2;
            d[0] = __float22bfloat162_rn(make_float2(f.x, f.y));
            d[1] = __float22bfloat162_rn(make_float2(f.z, f.w));
        } else {
            size_t j = i - NV4;
            float4 f = ((const float4*)W)[j];
            __nv_bfloat162* d = (__nv_bfloat162*)g_W16 + j*2;
            d[0] = __float22bfloat162_rn(make_float2(f.x, f.y));
            d[1] = __float22bfloat162_rn(make_float2(f.z, f.w));
        }
    }
}

// ---------------- kernel 2: GEMM + interleaved scan + fused rescore ----------------
__global__ __launch_bounds__(NTHREADS, 1)
void gemm_topk_kernel(const float* __restrict__ bias,
                      const float* __restrict__ V,
                      const float* __restrict__ W,
                      const float* __restrict__ pool,
                      float* __restrict__ out)
{
    extern __shared__ char smem[];
    const uint32_t sbase = s2u(smem);
    const int tid  = threadIdx.x;
    const int lane = tid & 31;
    const int wid  = tid >> 5;
    const int g    = lane >> 2;
    const int tq   = lane & 3;
    const int wm   = wid & 1;        // M half (64 rows)
    const int wn   = wid >> 1;       // N eighth (32 cols)
    const int row0 = blockIdx.x * BM;

    float* bias_s = (float*)(smem + SM_BIAS);
    float* lv_s   = (float*)(smem + SM_LV);
    int*   li_s   = (int*)(smem + SM_LI);

    if (tid < BM){
        #pragma unroll
        for (int k = 0; k < NCAND; ++k){
            lv_s[tid*NCAND + k] = -INFINITY;
            li_s[tid*NCAND + k] = 0;
        }
    }
    float thr = -INFINITY;

    // ldmatrix lane->row/k decomposition (swizzled 128B rows)
    const uint32_t aRow  = (uint32_t)(wm*64 + (lane & 15));        // + mi*16
    const uint32_t aKb   = (uint32_t)(lane >> 4);                  // k 16B-unit low bit
    const uint32_t aSw   = aRow & 7;                               // invariant under +16
    const uint32_t bRow  = (uint32_t)(wn*32 + (lane & 7) + ((lane & 16) >> 1)); // + nip*16
    const uint32_t bKb   = (uint32_t)((lane >> 3) & 1);
    const uint32_t bSw   = bRow & 7;

    // one chunk: A 128x128B + B 256x128B  (3072 x 16B cp.async, 6/thread)
    auto issue_chunk = [&](int c){
        const int nt = c / KCH;
        const int kt = c - nt * KCH;
        const uint32_t stg = sbase + (uint32_t)(c % NSTAGE) * STAGE_BYTES;
        #pragma unroll
        for (int i = 0; i < 2; ++i){     // A
            const int o = tid + i*512;
            const int r = o >> 3, kc = o & 7;
            cpa16(stg + (uint32_t)r*128u + (uint32_t)((kc ^ (r & 7)) << 4),
                  g_V16 + (size_t)(row0 + r)*DIM + kt*BK + kc*8);
        }
        #pragma unroll
        for (int i = 0; i < 4; ++i){     // B
            const int o = tid + i*512;
            const int r = o >> 3, kc = o & 7;
            cpa16(stg + A_STAGE_B + (uint32_t)r*128u + (uint32_t)((kc ^ (r & 7)) << 4),
                  g_W16 + (size_t)(nt*BN + r)*DIM + kt*BK + kc*8);
        }
        CPA_COMMIT();
    };

    // per-slice top-8 scan of previous tile's staged scores (threads 0..127)
    auto scan_slice = [&](int n0, int j0, int j1){
        const __nv_bfloat162* srow =
            (const __nv_bfloat162*)(smem + SM_SC + (size_t)tid*SC_STRIDE*2);
        const int base = tid * NCAND;
        for (int j = j0; j < j1; ++j){
            const float2 f = __bfloat1622float2(srow[j]);
            if (f.x > thr){
                int k = NCAND-1;
                while (k > 0 && lv_s[base+k-1] < f.x){
                    lv_s[base+k] = lv_s[base+k-1];
                    li_s[base+k] = li_s[base+k-1];
                    --k;
                }
                lv_s[base+k] = f.x; li_s[base+k] = n0 + 2*j;
                thr = lv_s[base+NCAND-1];
            }
            if (f.y > thr){
                int k = NCAND-1;
                while (k > 0 && lv_s[base+k-1] < f.y){
                    lv_s[base+k] = lv_s[base+k-1];
                    li_s[base+k] = li_s[base+k-1];
                    --k;
                }
                lv_s[base+k] = f.y; li_s[base+k] = n0 + 2*j + 1;
                thr = lv_s[base+NCAND-1];
            }
        }
    };

    issue_chunk(0); issue_chunk(1);    // prologue: 2 chunks in flight

    for (int nt = 0; nt < NT_TILES; ++nt){
        float acc[4][4][4];
        #pragma unroll
        for (int mi = 0; mi < 4; ++mi)
            #pragma unroll
            for (int ni = 0; ni < 4; ++ni)
                #pragma unroll
                for (int q = 0; q < 4; ++q) acc[mi][ni][q] = 0.0f;

        #pragma unroll 1
        for (int kt = 0; kt < KCH; ++kt){
            const int c = nt * KCH + kt;
            CPA_WAIT1();                 // chunk c resident (c+1 may be in flight)
            __syncthreads();
            if (kt == 0 && tid < 256) bias_s[tid] = bias[nt*BN + tid];

            if (c + 2 < NCHUNK) issue_chunk(c + 2);   // 2-ahead into stage (c+2)%3

            const uint32_t stg  = sbase + (uint32_t)(c % NSTAGE) * STAGE_BYTES;
            const uint32_t stgB = stg + A_STAGE_B;

            #pragma unroll
            for (int ks = 0; ks < 4; ++ks){   // four k16 steps per 128B row
                const uint32_t akx = ((uint32_t)(ks*2) + aKb) ^ aSw;
                const uint32_t bkx = ((uint32_t)(ks*2) + bKb) ^ bSw;
                uint32_t a[4][4], b[4][2];
                #pragma unroll
                for (int mi = 0; mi < 4; ++mi)
                    ldsm4(a[mi], stg + (aRow + mi*16)*128u + (akx << 4));
                #pragma unroll
                for (int nip = 0; nip < 2; ++nip){
                    uint32_t r4[4];
                    ldsm4(r4, stgB + (bRow + nip*16)*128u + (bkx << 4));
                    b[nip*2  ][0] = r4[0]; b[nip*2  ][1] = r4[1];
                    b[nip*2+1][0] = r4[2]; b[nip*2+1][1] = r4[3];
                }
                #pragma unroll
                for (int ni = 0; ni < 4; ++ni)
                    #pragma unroll
                    for (int mi = 0; mi < 4; ++mi)
                        mma16816(acc[mi][ni], a[mi], b[ni][0], b[ni][1]);
            }

            // interleaved scan of PREVIOUS tile's scores (fills stall bubbles)
            if (nt > 0 && tid < BM){
                const int j0 = kt * 11;
                const int j1 = (j0 + 11 < 128) ? (j0 + 11) : 128;
                scan_slice((nt-1) * BN, j0, j1);
            }
        }

        // ---- stage scores (offset bf16, bias folded) ----
        __syncthreads();   // all slice reads of sc (tile nt-1) complete
        #pragma unroll
        for (int mi = 0; mi < 4; ++mi){
            const int row = wm*64 + mi*16 + g;
            #pragma unroll
            for (int ni = 0; ni < 4; ++ni){
                const int col = wn*32 + ni*8 + 2*tq;
                const float b0 = bias_s[col]     - SCOFF;
                const float b1 = bias_s[col + 1] - SCOFF;
                __nv_bfloat162* p0 =
                    (__nv_bfloat162*)(smem + SM_SC + ((size_t)row*SC_STRIDE + col)*2);
                __nv_bfloat162* p1 =
                    (__nv_bfloat162*)(smem + SM_SC + ((size_t)(row+8)*SC_STRIDE + col)*2);
                *p0 = __float22bfloat162_rn(
                        make_float2(acc[mi][ni][0] + b0, acc[mi][ni][1] + b1));
                *p1 = __float22bfloat162_rn(
                        make_float2(acc[mi][ni][2] + b0, acc[mi][ni][3] + b1));
            }
        }
        // next tile's kt=0 __syncthreads orders these writes before slice reads
    }

    // ---- epilogue: scan the last tile, then exact rescore ----
    __syncthreads();
    if (tid < BM) scan_slice((NT_TILES-1) * BN, 0, 128);
    __syncthreads();

    {   // warps 0..15, 8 rows each: exact fp32 rescore + softmax + combine
        for (int rr = 0; rr < 8; ++rr){
            const int rloc = wid*8 + rr;
            const int row  = row0 + rloc;

            int ids[NCAND];
            #pragma unroll
            for (int k = 0; k < NCAND; ++k)
                ids[k] = li_s[rloc*NCAND + k];

            float4 a4[NCAND];
            #pragma unroll
            for (int k = 0; k < NCAND; ++k) a4[k] = make_float4(0.f,0.f,0.f,0.f);
            const float4* vrow = (const float4*)(V + (size_t)row * DIM);
            #pragma unroll
            for (int i = 0; i < DIM/128; ++i){
                const int d4 = i*32 + lane;
                const float4 v = vrow[d4];
                #pragma unroll
                for (int k = 0; k < NCAND; ++k){
                    const float4 w = __ldg((const float4*)(W + (size_t)ids[k]*DIM) + d4);
                    a4[k].x = fmaf(v.x, w.x, a4[k].x);
                    a4[k].y = fmaf(v.y, w.y, a4[k].y);
                    a4[k].z = fmaf(v.z, w.z, a4[k].z);
                    a4[k].w = fmaf(v.w, w.w, a4[k].w);
                }
            }
            float acc2[NCAND];
            #pragma unroll
            for (int k = 0; k < NCAND; ++k){
                float s = (a4[k].x + a4[k].y) + (a4[k].z + a4[k].w);
                #pragma unroll
                for (int off = 16; off; off >>= 1)
                    s += __shfl_xor_sync(0xffffffffu, s, off);
                acc2[k] = s + bias[ids[k]];
            }
            #pragma unroll
            for (int a = 0; a < NCAND; ++a)
                #pragma unroll
                for (int j = 0; j < NCAND-1; ++j)
                    if (acc2[j] < acc2[j+1]){
                        float tv = acc2[j]; acc2[j] = acc2[j+1]; acc2[j+1] = tv;
                        int   tx = ids[j];  ids[j]  = ids[j+1];  ids[j+1]  = tx;
                    }
            const float m = acc2[0];
            float e0 = expf(acc2[0]-m), e1 = expf(acc2[1]-m), e2 = expf(acc2[2]-m),
                  e3 = expf(acc2[3]-m), e4 = expf(acc2[4]-m);
            const float inv = 1.0f / (e0+e1+e2+e3+e4);
            e0 *= inv; e1 *= inv; e2 *= inv; e3 *= inv; e4 *= inv;
            const float4* p0 = (const float4*)(pool + (size_t)ids[0]*DIM);
            const float4* p1 = (const float4*)(pool + (size_t)ids[1]*DIM);
            const float4* p2 = (const float4*)(pool + (size_t)ids[2]*DIM);
            const float4* p3 = (const float4*)(pool + (size_t)ids[3]*DIM);
            const float4* p4 = (const float4*)(pool + (size_t)ids[4]*DIM);
            float4* orow = (float4*)(out + (size_t)row * DIM);
            #pragma unroll
            for (int i = 0; i < DIM/128; ++i){
                const int d4 = i*32 + lane;
                const float4 q0 = p0[d4], q1 = p1[d4], q2 = p2[d4],
                             q3 = p3[d4], q4 = p4[d4];
                float4 o;
                o.x = e0*q0.x; o.y = e0*q0.y; o.z = e0*q0.z; o.w = e0*q0.w;
                o.x = fmaf(e1,q1.x,o.x); o.y = fmaf(e1,q1.y,o.y); o.z = fmaf(e1,q1.z,o.z); o.w = fmaf(e1,q1.w,o.w);
                o.x = fmaf(e2,q2.x,o.x); o.y = fmaf(e2,q2.y,o.y); o.z = fmaf(e2,q2.z,o.z); o.w = fmaf(e2,q2.w,o.w);
                o.x = fmaf(e3,q3.x,o.x); o.y = fmaf(e3,q3.y,o.y); o.z = fmaf(e3,q3.z,o.z); o.w = fmaf(e3,q3.w,o.w);
                o.x = fmaf(e4,q4.x,o.x); o.y = fmaf(e4,q4.y,o.y); o.z = fmaf(e4,q4.z,o.z); o.w = fmaf(e4,q4.w,o.w);
                orow[d4] = o;
            }
        }
    }
}

// ---------------- launch ----------------
extern "C" void kernel_launch(void* const* d_in, const int* in_sizes, int n_in,
                              void* d_out, int out_size)
{
    const float* V    = (const float*)d_in[0];
    const float* W    = (const float*)d_in[1];
    const float* bias = (const float*)d_in[2];
    const float* pool = (const float*)d_in[3];
    float* out = (float*)d_out;

    cudaFuncSetAttribute(gemm_topk_kernel,
                         cudaFuncAttributeMaxDynamicSharedMemorySize, SM_TOTAL);

    dummy_kernel<<<1, 32>>>();
    dummy_kernel<<<1, 32>>>();
    convert_kernel<<<1184, 256>>>(V, W);
    gemm_topk_kernel<<<B_ROWS / BM, NTHREADS, SM_TOTAL>>>(bias, V, W, pool, out);
}

// round 15
// speedup vs baseline: 1.1120x; 1.0574x over previous
#include <cuda_runtime.h>
#include <cuda_bf16.h>
#include <math.h>
#include <stdint.h>

// ---------------- problem constants ----------------
#define B_ROWS 16384
#define DIM    768
#define NP     8192
#define NCAND  8            // candidates per row handed to rescore
#define SCOFF  3.0f

// ---------------- GEMM tiling ----------------
#define BM 128
#define BN 256
#define BK 64               // bf16 elems per chunk row (= 128 bytes)
#define NSTAGE 3
#define NTHREADS 512
#define NT_TILES (NP / BN)        // 32
#define KCH      (DIM / BK)       // 12
#define NCHUNK   (NT_TILES * KCH) // 384
#define APITCH_B 128              // bytes per smem row (swizzled, no pad)
#define A_STAGE_B (BM * APITCH_B)            // 16384
#define B_STAGE_B (BN * APITCH_B)            // 32768
#define STAGE_BYTES (A_STAGE_B + B_STAGE_B)  // 49152
#define SC_STRIDE 264             // bf16 elems per sc row

// smem layout (bytes)
#define SM_SC    (NSTAGE * STAGE_BYTES)              // 147456
#define SM_BIAS  (SM_SC + BM * SC_STRIDE * 2)        // 215040
#define SM_LV    (SM_BIAS + BN * 4)                  // 216064
#define SM_LI    (SM_LV + BM * NCAND * 4)            // 220160
#define SM_TOTAL (SM_LI + BM * NCAND * 4)            // 224256

// ---------------- device scratch ----------------
__device__ __nv_bfloat16 g_V16[(size_t)B_ROWS * DIM];
__device__ __nv_bfloat16 g_W16[(size_t)NP * DIM];
__device__ int           g_cand[(size_t)B_ROWS * NCAND];

// ---------------- helpers ----------------
static __device__ __forceinline__ uint32_t s2u(const void* p){
    uint32_t a;
    asm("{ .reg .u64 t; cvta.to.shared.u64 t, %1; cvt.u32.u64 %0, t; }"
        : "=r"(a) : "l"(p));
    return a;
}
static __device__ __forceinline__ void cpa16(uint32_t dst, const void* src){
    asm volatile("cp.async.cg.shared.global [%0], [%1], 16;"
        :: "r"(dst), "l"(src) : "memory");
}
#define CPA_COMMIT() asm volatile("cp.async.commit_group;" ::: "memory")
#define CPA_WAIT1()  asm volatile("cp.async.wait_group 1;" ::: "memory")

static __device__ __forceinline__ void ldsm4(uint32_t* r, uint32_t addr){
    asm volatile("ldmatrix.sync.aligned.m8n8.x4.shared.b16 {%0,%1,%2,%3}, [%4];"
        : "=r"(r[0]), "=r"(r[1]), "=r"(r[2]), "=r"(r[3]) : "r"(addr));
}
static __device__ __forceinline__ void mma16816(float* d, const uint32_t* a,
                                                uint32_t b0, uint32_t b1){
    asm volatile(
        "mma.sync.aligned.m16n8k16.row.col.f32.bf16.bf16.f32 "
        "{%0,%1,%2,%3}, {%4,%5,%6,%7}, {%8,%9}, {%0,%1,%2,%3};"
        : "+f"(d[0]), "+f"(d[1]), "+f"(d[2]), "+f"(d[3])
        : "r"(a[0]), "r"(a[1]), "r"(a[2]), "r"(a[3]), "r"(b0), "r"(b1));
}

// ---------------- kernel 0: dummy (ncu launch alignment) ----------------
__global__ void dummy_kernel() {}

// ---------------- kernel 1: fp32 -> bf16 convert ----------------
__global__ void convert_kernel(const float* __restrict__ V,
                               const float* __restrict__ W)
{
    const size_t NV4 = (size_t)B_ROWS * DIM / 4;
    const size_t NW4 = (size_t)NP * DIM / 4;
    const size_t stride = (size_t)gridDim.x * blockDim.x;
    for (size_t i = blockIdx.x * (size_t)blockDim.x + threadIdx.x;
         i < NV4 + NW4; i += stride){
        if (i < NV4){
            float4 f = ((const float4*)V)[i];
            __nv_bfloat162* d = (__nv_bfloat162*)g_V16 + i*2;
            d[0] = __float22bfloat162_rn(make_float2(f.x, f.y));
            d[1] = __float22bfloat162_rn(make_float2(f.z, f.w));
        } else {
            size_t j = i - NV4;
            float4 f = ((const float4*)W)[j];
            __nv_bfloat162* d = (__nv_bfloat162*)g_W16 + j*2;
            d[0] = __float22bfloat162_rn(make_float2(f.x, f.y));
            d[1] = __float22bfloat162_rn(make_float2(f.z, f.w));
        }
    }
}

// ---------------- kernel 2: bf16 mma.sync GEMM (ks-staggered) + top-8 scan ----------------
__global__ __launch_bounds__(NTHREADS, 1)
void gemm_topk_kernel(const float* __restrict__ bias)
{
    extern __shared__ char smem[];
    const uint32_t sbase = s2u(smem);
    const int tid  = threadIdx.x;
    const int lane = tid & 31;
    const int wid  = tid >> 5;
    const int g    = lane >> 2;
    const int tq   = lane & 3;
    const int wm   = wid & 1;        // M half (64 rows)
    const int wn   = wid >> 1;       // N eighth (32 cols)
    const int kso  = (wid >> 2) & 3; // per-warp ks phase offset (de-phases SMSP-mates)
    const int row0 = blockIdx.x * BM;

    float* bias_s = (float*)(smem + SM_BIAS);
    float* lv_s   = (float*)(smem + SM_LV);
    int*   li_s   = (int*)(smem + SM_LI);

    if (tid < BM){
        #pragma unroll
        for (int k = 0; k < NCAND; ++k){
            lv_s[tid*NCAND + k] = -INFINITY;
            li_s[tid*NCAND + k] = 0;
        }
    }
    float thr = -INFINITY;

    // ldmatrix lane->row/k decomposition (swizzled 128B rows)
    const uint32_t aRow  = (uint32_t)(wm*64 + (lane & 15));        // + mi*16
    const uint32_t aKb   = (uint32_t)(lane >> 4);                  // k 16B-unit low bit
    const uint32_t aSw   = aRow & 7;                               // invariant under +16
    const uint32_t bRow  = (uint32_t)(wn*32 + (lane & 7) + ((lane & 16) >> 1)); // + nip*16
    const uint32_t bKb   = (uint32_t)((lane >> 3) & 1);
    const uint32_t bSw   = bRow & 7;

    // one chunk: A 128x128B + B 256x128B  (3072 x 16B cp.async, 6/thread)
    auto issue_chunk = [&](int c){
        const int nt = c / KCH;
        const int kt = c - nt * KCH;
        const uint32_t stg = sbase + (uint32_t)(c % NSTAGE) * STAGE_BYTES;
        #pragma unroll
        for (int i = 0; i < 2; ++i){     // A
            const int o = tid + i*512;
            const int r = o >> 3, kc = o & 7;
            cpa16(stg + (uint32_t)r*128u + (uint32_t)((kc ^ (r & 7)) << 4),
                  g_V16 + (size_t)(row0 + r)*DIM + kt*BK + kc*8);
        }
        #pragma unroll
        for (int i = 0; i < 4; ++i){     // B
            const int o = tid + i*512;
            const int r = o >> 3, kc = o & 7;
            cpa16(stg + A_STAGE_B + (uint32_t)r*128u + (uint32_t)((kc ^ (r & 7)) << 4),
                  g_W16 + (size_t)(nt*BN + r)*DIM + kt*BK + kc*8);
        }
        CPA_COMMIT();
    };

    issue_chunk(0); issue_chunk(1);    // prologue: 2 chunks in flight

    for (int nt = 0; nt < NT_TILES; ++nt){
        float acc[4][4][4];
        #pragma unroll
        for (int mi = 0; mi < 4; ++mi)
            #pragma unroll
            for (int ni = 0; ni < 4; ++ni)
                #pragma unroll
                for (int q = 0; q < 4; ++q) acc[mi][ni][q] = 0.0f;

        #pragma unroll 1
        for (int kt = 0; kt < KCH; ++kt){
            const int c = nt * KCH + kt;
            CPA_WAIT1();                 // chunk c resident (c+1 may be in flight)
            __syncthreads();
            if (kt == 0 && tid < 256) bias_s[tid] = bias[nt*BN + tid];

            if (c + 2 < NCHUNK) issue_chunk(c + 2);   // 2-ahead into stage (c+2)%3

            const uint32_t stg  = sbase + (uint32_t)(c % NSTAGE) * STAGE_BYTES;
            const uint32_t stgB = stg + A_STAGE_B;

            #pragma unroll
            for (int jj = 0; jj < 4; ++jj){   // four k16 steps, per-warp rotated order
                const int ks = (jj + kso) & 3;
                const uint32_t akx = ((uint32_t)(ks*2) + aKb) ^ aSw;
                const uint32_t bkx = ((uint32_t)(ks*2) + bKb) ^ bSw;
                uint32_t a[4][4], b[4][2];
                #pragma unroll
                for (int mi = 0; mi < 4; ++mi)
                    ldsm4(a[mi], stg + (aRow + mi*16)*128u + (akx << 4));
                #pragma unroll
                for (int nip = 0; nip < 2; ++nip){
                    uint32_t r4[4];
                    ldsm4(r4, stgB + (bRow + nip*16)*128u + (bkx << 4));
                    b[nip*2  ][0] = r4[0]; b[nip*2  ][1] = r4[1];
                    b[nip*2+1][0] = r4[2]; b[nip*2+1][1] = r4[3];
                }
                #pragma unroll
                for (int ni = 0; ni < 4; ++ni)
                    #pragma unroll
                    for (int mi = 0; mi < 4; ++mi)
                        mma16816(acc[mi][ni], a[mi], b[ni][0], b[ni][1]);
            }
        }

        // ---- stage scores (offset bf16, bias folded) ----
        #pragma unroll
        for (int mi = 0; mi < 4; ++mi){
            const int row = wm*64 + mi*16 + g;
            #pragma unroll
            for (int ni = 0; ni < 4; ++ni){
                const int col = wn*32 + ni*8 + 2*tq;
                const float b0 = bias_s[col]     - SCOFF;
                const float b1 = bias_s[col + 1] - SCOFF;
                __nv_bfloat162* p0 =
                    (__nv_bfloat162*)(smem + SM_SC + ((size_t)row*SC_STRIDE + col)*2);
                __nv_bfloat162* p1 =
                    (__nv_bfloat162*)(smem + SM_SC + ((size_t)(row+8)*SC_STRIDE + col)*2);
                *p0 = __float22bfloat162_rn(
                        make_float2(acc[mi][ni][0] + b0, acc[mi][ni][1] + b1));
                *p1 = __float22bfloat162_rn(
                        make_float2(acc[mi][ni][2] + b0, acc[mi][ni][3] + b1));
            }
        }
        __syncthreads();

        // ---- per-row top-8 scan (threads 0..127) ----
        if (tid < BM){
            const __nv_bfloat162* srow =
                (const __nv_bfloat162*)(smem + SM_SC + (size_t)tid*SC_STRIDE*2);
            const int base = tid * NCAND;
            const int n0   = nt * BN;
            #pragma unroll 4
            for (int j = 0; j < BN/2; ++j){
                const float2 f = __bfloat1622float2(srow[j]);
                if (f.x > thr){
                    int k = NCAND-1;
                    while (k > 0 && lv_s[base+k-1] < f.x){
                        lv_s[base+k] = lv_s[base+k-1];
                        li_s[base+k] = li_s[base+k-1];
                        --k;
                    }
                    lv_s[base+k] = f.x; li_s[base+k] = n0 + 2*j;
                    thr = lv_s[base+NCAND-1];
                }
                if (f.y > thr){
                    int k = NCAND-1;
                    while (k > 0 && lv_s[base+k-1] < f.y){
                        lv_s[base+k] = lv_s[base+k-1];
                        li_s[base+k] = li_s[base+k-1];
                        --k;
                    }
                    lv_s[base+k] = f.y; li_s[base+k] = n0 + 2*j + 1;
                    thr = lv_s[base+NCAND-1];
                }
            }
        }
        __syncthreads();
    }

    if (tid < BM){
        #pragma unroll
        for (int k = 0; k < NCAND; ++k)
            g_cand[(size_t)(row0 + tid)*NCAND + k] = li_s[tid*NCAND + k];
    }
}

// ---------------- kernel 3: exact rescore + softmax + combine (float4) ----------------
__global__ __launch_bounds__(256)
void rescore_kernel(const float* __restrict__ V,
                    const float* __restrict__ W,
                    const float* __restrict__ bias,
                    const float* __restrict__ pool,
                    float* __restrict__ out)
{
    const int lane = threadIdx.x & 31;
    const int wid  = threadIdx.x >> 5;
    const int row  = blockIdx.x * 8 + wid;

    int ids[NCAND];
    #pragma unroll
    for (int k = 0; k < NCAND; ++k)
        ids[k] = g_cand[(size_t)row*NCAND + k];

    float4 a4[NCAND];
    #pragma unroll
    for (int k = 0; k < NCAND; ++k) a4[k] = make_float4(0.f, 0.f, 0.f, 0.f);
    const float4* vrow = (const float4*)(V + (size_t)row * DIM);
    #pragma unroll
    for (int i = 0; i < DIM/128; ++i){
        const int d4 = i*32 + lane;
        const float4 v = vrow[d4];
        #pragma unroll
        for (int k = 0; k < NCAND; ++k){
            const float4 w = __ldg((const float4*)(W + (size_t)ids[k]*DIM) + d4);
            a4[k].x = fmaf(v.x, w.x, a4[k].x);
            a4[k].y = fmaf(v.y, w.y, a4[k].y);
            a4[k].z = fmaf(v.z, w.z, a4[k].z);
            a4[k].w = fmaf(v.w, w.w, a4[k].w);
        }
    }
    float acc[NCAND];
    #pragma unroll
    for (int k = 0; k < NCAND; ++k){
        float s = (a4[k].x + a4[k].y) + (a4[k].z + a4[k].w);
        #pragma unroll
        for (int off = 16; off; off >>= 1)
            s += __shfl_xor_sync(0xffffffffu, s, off);
        acc[k] = s + bias[ids[k]];
    }
    #pragma unroll
    for (int a = 0; a < NCAND; ++a)
        #pragma unroll
        for (int j = 0; j < NCAND-1; ++j)
            if (acc[j] < acc[j+1]){
                float tv = acc[j]; acc[j] = acc[j+1]; acc[j+1] = tv;
                int   tx = ids[j]; ids[j] = ids[j+1]; ids[j+1] = tx;
            }
    const float m = acc[0];
    float e0 = expf(acc[0]-m), e1 = expf(acc[1]-m), e2 = expf(acc[2]-m),
          e3 = expf(acc[3]-m), e4 = expf(acc[4]-m);
    const float inv = 1.0f / (e0+e1+e2+e3+e4);
    e0 *= inv; e1 *= inv; e2 *= inv; e3 *= inv; e4 *= inv;
    const float4* p0 = (const float4*)(pool + (size_t)ids[0]*DIM);
    const float4* p1 = (const float4*)(pool + (size_t)ids[1]*DIM);
    const float4* p2 = (const float4*)(pool + (size_t)ids[2]*DIM);
    const float4* p3 = (const float4*)(pool + (size_t)ids[3]*DIM);
    const float4* p4 = (const float4*)(pool + (size_t)ids[4]*DIM);
    float4* orow = (float4*)(out + (size_t)row * DIM);
    #pragma unroll
    for (int i = 0; i < DIM/128; ++i){
        const int d4 = i*32 + lane;
        const float4 q0 = p0[d4], q1 = p1[d4], q2 = p2[d4], q3 = p3[d4], q4 = p4[d4];
        float4 o;
        o.x = e0*q0.x; o.y = e0*q0.y; o.z = e0*q0.z; o.w = e0*q0.w;
        o.x = fmaf(e1,q1.x,o.x); o.y = fmaf(e1,q1.y,o.y); o.z = fmaf(e1,q1.z,o.z); o.w = fmaf(e1,q1.w,o.w);
        o.x = fmaf(e2,q2.x,o.x); o.y = fmaf(e2,q2.y,o.y); o.z = fmaf(e2,q2.z,o.z); o.w = fmaf(e2,q2.w,o.w);
        o.x = fmaf(e3,q3.x,o.x); o.y = fmaf(e3,q3.y,o.y); o.z = fmaf(e3,q3.z,o.z); o.w = fmaf(e3,q3.w,o.w);
        o.x = fmaf(e4,q4.x,o.x); o.y = fmaf(e4,q4.y,o.y); o.z = fmaf(e4,q4.z,o.z); o.w = fmaf(e4,q4.w,o.w);
        orow[d4] = o;
    }
}

// ---------------- launch ----------------
extern "C" void kernel_launch(void* const* d_in, const int* in_sizes, int n_in,
                              void* d_out, int out_size)
{
    const float* V    = (const float*)d_in[0];
    const float* W    = (const float*)d_in[1];
    const float* bias = (const float*)d_in[2];
    const float* pool = (const float*)d_in[3];
    float* out = (float*)d_out;

    cudaFuncSetAttribute(gemm_topk_kernel,
                         cudaFuncAttributeMaxDynamicSharedMemorySize, SM_TOTAL);

    dummy_kernel<<<1, 32>>>();
    dummy_kernel<<<1, 32>>>();
    convert_kernel<<<1184, 256>>>(V, W);
    gemm_topk_kernel<<<B_ROWS / BM, NTHREADS, SM_TOTAL>>>(bias);   // launch #4 -> ncu
    rescore_kernel<<<B_ROWS / 8, 256>>>(V, W, bias, pool, out);
}

// round 16
// speedup vs baseline: 1.3175x; 1.1848x over previous
#include <cuda_runtime.h>
#include <cuda_bf16.h>
#include <math.h>
#include <stdint.h>

// ---------------- problem constants ----------------
#define B_ROWS 16384
#define DIM    768
#define NP     8192
#define NHALF  (NP/2)       // 4096 prompts per CTA (N-half)
#define NCAND  8            // per-half candidates per row
#define NCTOT  16           // total candidates handed to rescore
#define SCOFF  3.0f

// ---------------- GEMM tiling ----------------
#define BM 128
#define BN 128
#define BK 64               // bf16 elems per chunk row (= 128 bytes)
#define NSTAGE 2
#define NTHREADS 256
#define NT_TILES (NHALF / BN)     // 32
#define KCH      (DIM / BK)       // 12
#define NCHUNK   (NT_TILES * KCH) // 384
#define APITCH_B 128              // bytes per smem row (swizzled, no pad)
#define A_STAGE_B (BM * APITCH_B)            // 16384
#define B_STAGE_B (BN * APITCH_B)            // 16384
#define STAGE_BYTES (A_STAGE_B + B_STAGE_B)  // 32768
#define SC_STRIDE 136             // bf16 elems per sc row (272B)

// smem layout (bytes)
#define SM_SC    (NSTAGE * STAGE_BYTES)              // 65536
#define SM_BIAS  (SM_SC + BM * SC_STRIDE * 2)        // 100352
#define SM_LV    (SM_BIAS + BN * 4)                  // 100864
#define SM_LI    (SM_LV + BM * NCAND * 4)            // 104960
#define SM_TOTAL (SM_LI + BM * NCAND * 4)            // 109056  (x2 CTA = 218112 <= 227KB)

// ---------------- device scratch ----------------
__device__ __nv_bfloat16 g_V16[(size_t)B_ROWS * DIM];
__device__ __nv_bfloat16 g_W16[(size_t)NP * DIM];
__device__ int           g_cand[(size_t)B_ROWS * NCTOT];

// ---------------- helpers ----------------
static __device__ __forceinline__ uint32_t s2u(const void* p){
    uint32_t a;
    asm("{ .reg .u64 t; cvta.to.shared.u64 t, %1; cvt.u32.u64 %0, t; }"
        : "=r"(a) : "l"(p));
    return a;
}
static __device__ __forceinline__ void cpa16(uint32_t dst, const void* src){
    asm volatile("cp.async.cg.shared.global [%0], [%1], 16;"
        :: "r"(dst), "l"(src) : "memory");
}
#define CPA_COMMIT() asm volatile("cp.async.commit_group;" ::: "memory")
#define CPA_WAIT0()  asm volatile("cp.async.wait_group 0;" ::: "memory")

static __device__ __forceinline__ void ldsm4(uint32_t* r, uint32_t addr){
    asm volatile("ldmatrix.sync.aligned.m8n8.x4.shared.b16 {%0,%1,%2,%3}, [%4];"
        : "=r"(r[0]), "=r"(r[1]), "=r"(r[2]), "=r"(r[3]) : "r"(addr));
}
static __device__ __forceinline__ void mma16816(float* d, const uint32_t* a,
                                                uint32_t b0, uint32_t b1){
    asm volatile(
        "mma.sync.aligned.m16n8k16.row.col.f32.bf16.bf16.f32 "
        "{%0,%1,%2,%3}, {%4,%5,%6,%7}, {%8,%9}, {%0,%1,%2,%3};"
        : "+f"(d[0]), "+f"(d[1]), "+f"(d[2]), "+f"(d[3])
        : "r"(a[0]), "r"(a[1]), "r"(a[2]), "r"(a[3]), "r"(b0), "r"(b1));
}

// ---------------- kernel 0: dummy (ncu launch alignment) ----------------
__global__ void dummy_kernel() {}

// ---------------- kernel 1: fp32 -> bf16 convert ----------------
__global__ void convert_kernel(const float* __restrict__ V,
                               const float* __restrict__ W)
{
    const size_t NV4 = (size_t)B_ROWS * DIM / 4;
    const size_t NW4 = (size_t)NP * DIM / 4;
    const size_t stride = (size_t)gridDim.x * blockDim.x;
    for (size_t i = blockIdx.x * (size_t)blockDim.x + threadIdx.x;
         i < NV4 + NW4; i += stride){
        if (i < NV4){
            float4 f = ((const float4*)V)[i];
            __nv_bfloat162* d = (__nv_bfloat162*)g_V16 + i*2;
            d[0] = __float22bfloat162_rn(make_float2(f.x, f.y));
            d[1] = __float22bfloat162_rn(make_float2(f.z, f.w));
        } else {
            size_t j = i - NV4;
            float4 f = ((const float4*)W)[j];
            __nv_bfloat162* d = (__nv_bfloat162*)g_W16 + j*2;
            d[0] = __float22bfloat162_rn(make_float2(f.x, f.y));
            d[1] = __float22bfloat162_rn(make_float2(f.z, f.w));
        }
    }
}

// ---------------- kernel 2: bf16 mma.sync GEMM, 2 CTAs/SM, N-halved ----------------
__global__ __launch_bounds__(NTHREADS, 2)
void gemm_topk_kernel(const float* __restrict__ bias)
{
    extern __shared__ char smem[];
    const uint32_t sbase = s2u(smem);
    const int tid  = threadIdx.x;
    const int lane = tid & 31;
    const int wid  = tid >> 5;
    const int g    = lane >> 2;
    const int tq   = lane & 3;
    const int wm   = wid & 1;        // M half (64 rows)
    const int wn   = wid >> 1;       // N quarter (32 cols)
    const int rowblk = blockIdx.x & 127;
    const int half   = blockIdx.x >> 7;
    const int row0   = rowblk * BM;
    const int nbase  = half * NHALF;

    float* bias_s = (float*)(smem + SM_BIAS);
    float* lv_s   = (float*)(smem + SM_LV);
    int*   li_s   = (int*)(smem + SM_LI);

    if (tid < BM){
        #pragma unroll
        for (int k = 0; k < NCAND; ++k){
            lv_s[tid*NCAND + k] = -INFINITY;
            li_s[tid*NCAND + k] = 0;
        }
    }
    float thr = -INFINITY;

    // ldmatrix lane->row/k decomposition (swizzled 128B rows)
    const uint32_t aRow  = (uint32_t)(wm*64 + (lane & 15));        // + mi*16
    const uint32_t aKb   = (uint32_t)(lane >> 4);                  // k 16B-unit low bit
    const uint32_t aSw   = aRow & 7;                               // invariant under +16
    const uint32_t bRow  = (uint32_t)(wn*32 + (lane & 7) + ((lane & 16) >> 1)); // + nip*16
    const uint32_t bKb   = (uint32_t)((lane >> 3) & 1);
    const uint32_t bSw   = bRow & 7;

    // one chunk: A 128x128B + B 128x128B  (2048 x 16B cp.async, 8/thread)
    auto issue_chunk = [&](int c){
        const int nt = c / KCH;
        const int kt = c - nt * KCH;
        const uint32_t stg = sbase + (uint32_t)(c & 1) * STAGE_BYTES;
        #pragma unroll
        for (int i = 0; i < 4; ++i){     // A
            const int o = tid + i*256;
            const int r = o >> 3, kc = o & 7;
            cpa16(stg + (uint32_t)r*128u + (uint32_t)((kc ^ (r & 7)) << 4),
                  g_V16 + (size_t)(row0 + r)*DIM + kt*BK + kc*8);
        }
        #pragma unroll
        for (int i = 0; i < 4; ++i){     // B
            const int o = tid + i*256;
            const int r = o >> 3, kc = o & 7;
            cpa16(stg + A_STAGE_B + (uint32_t)r*128u + (uint32_t)((kc ^ (r & 7)) << 4),
                  g_W16 + (size_t)(nbase + nt*BN + r)*DIM + kt*BK + kc*8);
        }
        CPA_COMMIT();
    };

    issue_chunk(0);    // prologue (double buffer)

    for (int nt = 0; nt < NT_TILES; ++nt){
        float acc[4][4][4];
        #pragma unroll
        for (int mi = 0; mi < 4; ++mi)
            #pragma unroll
            for (int ni = 0; ni < 4; ++ni)
                #pragma unroll
                for (int q = 0; q < 4; ++q) acc[mi][ni][q] = 0.0f;

        #pragma unroll 1
        for (int kt = 0; kt < KCH; ++kt){
            const int c = nt * KCH + kt;
            CPA_WAIT0();                 // chunk c resident
            __syncthreads();             // reads of other stage done
            if (kt == 0 && tid < BN) bias_s[tid] = bias[nbase + nt*BN + tid];

            if (c + 1 < NCHUNK) issue_chunk(c + 1);   // into other stage

            const uint32_t stg  = sbase + (uint32_t)(c & 1) * STAGE_BYTES;
            const uint32_t stgB = stg + A_STAGE_B;

            #pragma unroll
            for (int ks = 0; ks < 4; ++ks){   // four k16 steps per 128B row
                const uint32_t akx = ((uint32_t)(ks*2) + aKb) ^ aSw;
                const uint32_t bkx = ((uint32_t)(ks*2) + bKb) ^ bSw;
                uint32_t a[4][4], b[4][2];
                #pragma unroll
                for (int mi = 0; mi < 4; ++mi)
                    ldsm4(a[mi], stg + (aRow + mi*16)*128u + (akx << 4));
                #pragma unroll
                for (int nip = 0; nip < 2; ++nip){
                    uint32_t r4[4];
                    ldsm4(r4, stgB + (bRow + nip*16)*128u + (bkx << 4));
                    b[nip*2  ][0] = r4[0]; b[nip*2  ][1] = r4[1];
                    b[nip*2+1][0] = r4[2]; b[nip*2+1][1] = r4[3];
                }
                #pragma unroll
                for (int ni = 0; ni < 4; ++ni)
                    #pragma unroll
                    for (int mi = 0; mi < 4; ++mi)
                        mma16816(acc[mi][ni], a[mi], b[ni][0], b[ni][1]);
            }
        }

        // ---- stage scores (offset bf16, bias folded) ----
        #pragma unroll
        for (int mi = 0; mi < 4; ++mi){
            const int row = wm*64 + mi*16 + g;
            #pragma unroll
            for (int ni = 0; ni < 4; ++ni){
                const int col = wn*32 + ni*8 + 2*tq;
                const float b0 = bias_s[col]     - SCOFF;
                const float b1 = bias_s[col + 1] - SCOFF;
                __nv_bfloat162* p0 =
                    (__nv_bfloat162*)(smem + SM_SC + ((size_t)row*SC_STRIDE + col)*2);
                __nv_bfloat162* p1 =
                    (__nv_bfloat162*)(smem + SM_SC + ((size_t)(row+8)*SC_STRIDE + col)*2);
                *p0 = __float22bfloat162_rn(
                        make_float2(acc[mi][ni][0] + b0, acc[mi][ni][1] + b1));
                *p1 = __float22bfloat162_rn(
                        make_float2(acc[mi][ni][2] + b0, acc[mi][ni][3] + b1));
            }
        }
        __syncthreads();

        // ---- per-row top-8 scan (threads 0..127) ----
        if (tid < BM){
            const __nv_bfloat162* srow =
                (const __nv_bfloat162*)(smem + SM_SC + (size_t)tid*SC_STRIDE*2);
            const int base = tid * NCAND;
            const int n0   = nbase + nt * BN;
            #pragma unroll 4
            for (int j = 0; j < BN/2; ++j){
                const float2 f = __bfloat1622float2(srow[j]);
                if (f.x > thr){
                    int k = NCAND-1;
                    while (k > 0 && lv_s[base+k-1] < f.x){
                        lv_s[base+k] = lv_s[base+k-1];
                        li_s[base+k] = li_s[base+k-1];
                        --k;
                    }
                    lv_s[base+k] = f.x; li_s[base+k] = n0 + 2*j;
                    thr = lv_s[base+NCAND-1];
                }
                if (f.y > thr){
                    int k = NCAND-1;
                    while (k > 0 && lv_s[base+k-1] < f.y){
                        lv_s[base+k] = lv_s[base+k-1];
                        li_s[base+k] = li_s[base+k-1];
                        --k;
                    }
                    lv_s[base+k] = f.y; li_s[base+k] = n0 + 2*j + 1;
                    thr = lv_s[base+NCAND-1];
                }
            }
        }
        __syncthreads();
    }

    if (tid < BM){
        #pragma unroll
        for (int k = 0; k < NCAND; ++k)
            g_cand[(size_t)(row0 + tid)*NCTOT + half*NCAND + k] = li_s[tid*NCAND + k];
    }
}

// ---------------- kernel 3: exact rescore (16 cands) + softmax + combine ----------------
__global__ __launch_bounds__(256)
void rescore_kernel(const float* __restrict__ V,
                    const float* __restrict__ W,
                    const float* __restrict__ bias,
                    const float* __restrict__ pool,
                    float* __restrict__ out)
{
    const int lane = threadIdx.x & 31;
    const int wid  = threadIdx.x >> 5;
    const int row  = blockIdx.x * 8 + wid;

    int ids[NCTOT];
    #pragma unroll
    for (int k = 0; k < NCTOT; ++k)
        ids[k] = g_cand[(size_t)row*NCTOT + k];

    float4 a4[NCTOT];
    #pragma unroll
    for (int k = 0; k < NCTOT; ++k) a4[k] = make_float4(0.f, 0.f, 0.f, 0.f);
    const float4* vrow = (const float4*)(V + (size_t)row * DIM);
    #pragma unroll 1
    for (int i = 0; i < DIM/128; ++i){
        const int d4 = i*32 + lane;
        const float4 v = vrow[d4];
        #pragma unroll
        for (int k = 0; k < NCTOT; ++k){
            const float4 w = __ldg((const float4*)(W + (size_t)ids[k]*DIM) + d4);
            a4[k].x = fmaf(v.x, w.x, a4[k].x);
            a4[k].y = fmaf(v.y, w.y, a4[k].y);
            a4[k].z = fmaf(v.z, w.z, a4[k].z);
            a4[k].w = fmaf(v.w, w.w, a4[k].w);
        }
    }
    float acc[NCTOT];
    #pragma unroll
    for (int k = 0; k < NCTOT; ++k){
        float s = (a4[k].x + a4[k].y) + (a4[k].z + a4[k].w);
        #pragma unroll
        for (int off = 16; off; off >>= 1)
            s += __shfl_xor_sync(0xffffffffu, s, off);
        acc[k] = s + bias[ids[k]];
    }
    #pragma unroll
    for (int a = 0; a < NCTOT; ++a)
        #pragma unroll
        for (int j = 0; j < NCTOT-1; ++j)
            if (acc[j] < acc[j+1]){
                float tv = acc[j]; acc[j] = acc[j+1]; acc[j+1] = tv;
                int   tx = ids[j]; ids[j] = ids[j+1]; ids[j+1] = tx;
            }
    const float m = acc[0];
    float e0 = expf(acc[0]-m), e1 = expf(acc[1]-m), e2 = expf(acc[2]-m),
          e3 = expf(acc[3]-m), e4 = expf(acc[4]-m);
    const float inv = 1.0f / (e0+e1+e2+e3+e4);
    e0 *= inv; e1 *= inv; e2 *= inv; e3 *= inv; e4 *= inv;
    const float4* p0 = (const float4*)(pool + (size_t)ids[0]*DIM);
    const float4* p1 = (const float4*)(pool + (size_t)ids[1]*DIM);
    const float4* p2 = (const float4*)(pool + (size_t)ids[2]*DIM);
    const float4* p3 = (const float4*)(pool + (size_t)ids[3]*DIM);
    const float4* p4 = (const float4*)(pool + (size_t)ids[4]*DIM);
    float4* orow = (float4*)(out + (size_t)row * DIM);
    #pragma unroll
    for (int i = 0; i < DIM/128; ++i){
        const int d4 = i*32 + lane;
        const float4 q0 = p0[d4], q1 = p1[d4], q2 = p2[d4], q3 = p3[d4], q4 = p4[d4];
        float4 o;
        o.x = e0*q0.x; o.y = e0*q0.y; o.z = e0*q0.z; o.w = e0*q0.w;
        o.x = fmaf(e1,q1.x,o.x); o.y = fmaf(e1,q1.y,o.y); o.z = fmaf(e1,q1.z,o.z); o.w = fmaf(e1,q1.w,o.w);
        o.x = fmaf(e2,q2.x,o.x); o.y = fmaf(e2,q2.y,o.y); o.z = fmaf(e2,q2.z,o.z); o.w = fmaf(e2,q2.w,o.w);
        o.x = fmaf(e3,q3.x,o.x); o.y = fmaf(e3,q3.y,o.y); o.z = fmaf(e3,q3.z,o.z); o.w = fmaf(e3,q3.w,o.w);
        o.x = fmaf(e4,q4.x,o.x); o.y = fmaf(e4,q4.y,o.y); o.z = fmaf(e4,q4.z,o.z); o.w = fmaf(e4,q4.w,o.w);
        orow[d4] = o;
    }
}

// ---------------- launch ----------------
extern "C" void kernel_launch(void* const* d_in, const int* in_sizes, int n_in,
                              void* d_out, int out_size)
{
    const float* V    = (const float*)d_in[0];
    const float* W    = (const float*)d_in[1];
    const float* bias = (const float*)d_in[2];
    const float* pool = (const float*)d_in[3];
    float* out = (float*)d_out;

    cudaFuncSetAttribute(gemm_topk_kernel,
                         cudaFuncAttributeMaxDynamicSharedMemorySize, SM_TOTAL);

    dummy_kernel<<<1, 32>>>();
    dummy_kernel<<<1, 32>>>();
    convert_kernel<<<1184, 256>>>(V, W);
    gemm_topk_kernel<<<(B_ROWS / BM) * 2, NTHREADS, SM_TOTAL>>>(bias);  // launch #4 -> ncu
    rescore_kernel<<<B_ROWS / 8, 256>>>(V, W, bias, pool, out);
}